// round 3
// baseline (speedup 1.0000x reference)
#include <cuda_runtime.h>

// X-gate on qubit 6 of 13 (op = I_64 ⊗ X ⊗ I_64) applied to two (2048, 8192)
// fp32 tensors. op is a permutation: out[:, j] = in[:, j ^ 64]; in float4
// index space out4[i] = in4[i ^ 16]. Pure streaming permuted copy.
//
// R2: 4 independent float4 loads/thread (MLP=4), exact-fit grid (no bounds
// checks, branchless half selection), __ldcs/__stcs streaming hints.

static constexpr long long BATCH   = 2048;
static constexpr long long DIM     = 8192;
static constexpr long long N4_PER  = BATCH * DIM / 4;   // 4,194,304 float4 per tensor
static constexpr long long N4_TOT  = 2 * N4_PER;        // 8,388,608
static constexpr int       THREADS = 256;
static constexpr int       ELEMS   = 4;                 // float4 per thread
static constexpr long long CHUNK   = N4_TOT / ELEMS;    // 2,097,152 (= N4_PER/2)
static constexpr int       BLOCKS  = (int)(CHUNK / THREADS);  // 8192

__global__ __launch_bounds__(THREADS) void xgate_permute_kernel(
    const float4* __restrict__ x0,
    const float4* __restrict__ x1,
    float4* __restrict__ out)
{
    const long long t = (long long)blockIdx.x * THREADS + threadIdx.x;

    // Chunk k covers [k*CHUNK, (k+1)*CHUNK). CHUNK == N4_PER/2, so chunks
    // 0,1 read x0 and chunks 2,3 read x1, resolved at compile time.
    const long long i0 = t;                 // x0
    const long long i1 = t + CHUNK;         // x0
    const long long i2 = t + 2 * CHUNK;     // x1
    const long long i3 = t + 3 * CHUNK;     // x1

    // XOR bit 4 of the float4 index (swap 64-float column groups). CHUNK and
    // N4_PER have bit 4 clear, so the XOR commutes with the offsets.
    float4 v0 = __ldcs(&x0[i0 ^ 16]);
    float4 v1 = __ldcs(&x0[(i1 ^ 16)]);
    float4 v2 = __ldcs(&x1[(i2 ^ 16) - N4_PER]);
    float4 v3 = __ldcs(&x1[(i3 ^ 16) - N4_PER]);

    __stcs(&out[i0], v0);
    __stcs(&out[i1], v1);
    __stcs(&out[i2], v2);
    __stcs(&out[i3], v3);
}

extern "C" void kernel_launch(void* const* d_in, const int* in_sizes, int n_in,
                              void* d_out, int out_size)
{
    const float4* x0 = (const float4*)d_in[0];
    const float4* x1 = (const float4*)d_in[1];
    // d_in[2] is op — ignored (fixed permutation).
    float4* out = (float4*)d_out;

    xgate_permute_kernel<<<BLOCKS, THREADS>>>(x0, x1, out);
}

// round 4
// speedup vs baseline: 1.0272x; 1.0272x over previous
#include <cuda_runtime.h>

// X-gate on qubit 6 of 13 (op = I_64 ⊗ X ⊗ I_64) applied to two (2048, 8192)
// fp32 tensors. op is a permutation: out[:, j] = in[:, j ^ 64]; in float4
// index space out4[i] = in4[i ^ 16]. Pure streaming permuted copy.
//
// R3: MLP=8 (8 front-batched LDG.128 per thread), 32-bit indexing,
// exact-fit grid, streaming hints. All offsets/chunk strides have bit 4
// clear so XOR-16 commutes with them; half-selection is compile-time.

static constexpr int BATCH   = 2048;
static constexpr int DIM     = 8192;
static constexpr int N4_PER  = BATCH * (DIM / 4);      // 4,194,304 float4 per tensor
static constexpr int N4_TOT  = 2 * N4_PER;             // 8,388,608
static constexpr int THREADS = 256;
static constexpr int ELEMS   = 8;                      // float4 per thread
static constexpr int CHUNK   = N4_TOT / ELEMS;         // 1,048,576 (= N4_PER/4)
static constexpr int BLOCKS  = CHUNK / THREADS;        // 4096

__global__ __launch_bounds__(THREADS) void xgate_permute_kernel(
    const float4* __restrict__ x0,
    const float4* __restrict__ x1,
    float4* __restrict__ out)
{
    const int t = blockIdx.x * THREADS + threadIdx.x;
    const int p = t ^ 16;   // XOR bit 4 of float4 index (swap 64-float groups)

    // Chunks 0..3 read x0, chunks 4..7 read x1 (CHUNK = N4_PER/4).
    // Front-batch all 8 loads for maximum memory-level parallelism.
    float4 v0 = __ldcs(&x0[p + 0 * CHUNK]);
    float4 v1 = __ldcs(&x0[p + 1 * CHUNK]);
    float4 v2 = __ldcs(&x0[p + 2 * CHUNK]);
    float4 v3 = __ldcs(&x0[p + 3 * CHUNK]);
    float4 v4 = __ldcs(&x1[p + 0 * CHUNK]);
    float4 v5 = __ldcs(&x1[p + 1 * CHUNK]);
    float4 v6 = __ldcs(&x1[p + 2 * CHUNK]);
    float4 v7 = __ldcs(&x1[p + 3 * CHUNK]);

    __stcs(&out[t + 0 * CHUNK], v0);
    __stcs(&out[t + 1 * CHUNK], v1);
    __stcs(&out[t + 2 * CHUNK], v2);
    __stcs(&out[t + 3 * CHUNK], v3);
    __stcs(&out[t + 4 * CHUNK], v4);
    __stcs(&out[t + 5 * CHUNK], v5);
    __stcs(&out[t + 6 * CHUNK], v6);
    __stcs(&out[t + 7 * CHUNK], v7);
}

extern "C" void kernel_launch(void* const* d_in, const int* in_sizes, int n_in,
                              void* d_out, int out_size)
{
    const float4* x0 = (const float4*)d_in[0];
    const float4* x1 = (const float4*)d_in[1];
    // d_in[2] is op — ignored (fixed permutation).
    float4* out = (float4*)d_out;

    xgate_permute_kernel<<<BLOCKS, THREADS>>>(x0, x1, out);
}